// round 17
// baseline (speedup 1.0000x reference)
#include <cuda_runtime.h>
#include <cuda_fp16.h>
#include <math.h>

#define D 64
#define DTXT 384
typedef unsigned long long ull;

#define MAXE (4 * 1024 * 1024)
#define MAXN 131072
#define SCHUNK 2048
#define NSHARD 4

// Scratch (static __device__ per harness rules)
__device__ unsigned g_edgesM[MAXE];        // packed (val_q15 << 17) | col
__device__ unsigned g_edgesA[MAXE];
__device__ int    g_rankM[MAXE];
__device__ int    g_rankA[MAXE];
__device__ __half g_embHM[MAXN * D];
__device__ __half g_embHA[MAXN * D];
__device__ __half g_xh[6][MAXN * D];       // x1..x3 for graph M (0..2) and A (3..5)
__device__ int    g_rowptrM[MAXN + 1];
__device__ int    g_rowptrA[MAXN + 1];
__device__ int    g_cnt[2 * NSHARD * MAXN];   // sharded counters [graph][shard][row]
__device__ int    g_sb[2 * NSHARD * MAXN];    // shard base offsets [graph][shard][row]
__device__ int    g_part[1024];
__device__ __half g_wt[D * DTXT];          // W transposed [n][k], fp16

// -------------------- W -> fp16, transposed to [n][k], once --------------------
__global__ void k_prepw(const float* __restrict__ W, __half* __restrict__ wt, int n) {
    int i = blockIdx.x * blockDim.x + threadIdx.x;
    if (i < n) {
        int nn = i / DTXT;
        int kk = i - nn * DTXT;
        wt[i] = __float2half_rn(W[kk * D + nn]);
    }
}

// -------------------- fp32 -> fp16 convert (both embs, blockIdx.y = graph) -----------
__global__ void k_prephalf2(const float4* __restrict__ me, const float4* __restrict__ ae,
                            uint2* __restrict__ dm, uint2* __restrict__ da,
                            int n4m, int n4a) {
    const float4* src; uint2* dst; int n4;
    if (blockIdx.y == 0) { src = me; dst = dm; n4 = n4m; }
    else                 { src = ae; dst = da; n4 = n4a; }
    int i = blockIdx.x * blockDim.x + threadIdx.x;
    if (i < n4) {
        float4 v = __ldg(src + i);
        __half2 h0 = __floats2half2_rn(v.x, v.y);
        __half2 h1 = __floats2half2_rn(v.z, v.w);
        uint2 o;
        o.x = *(unsigned*)&h0;
        o.y = *(unsigned*)&h1;
        dst[i] = o;
    }
}

// -------------------- SHARDED histogram + rank capture, 4 edges/thread ---------------
// Shard s = (e0>>2)&3 — deterministic from edge index, recomputed in scatter.
__global__ void k_hist4(const int* __restrict__ mr, const int* __restrict__ ar,
                        int* __restrict__ cntAll,
                        int* __restrict__ rkM, int* __restrict__ rkA,
                        int Em, int Ea) {
    const int* rowp; int* cntBase; int* rk; int E;
    if (blockIdx.y == 0) { rowp = mr; cntBase = cntAll;                  rk = rkM; E = Em; }
    else                 { rowp = ar; cntBase = cntAll + NSHARD * MAXN;  rk = rkA; E = Ea; }
    int t = blockIdx.x * blockDim.x + threadIdx.x;
    int e0 = t * 4;
    int* cnt = cntBase + (t & (NSHARD - 1)) * MAXN;   // shard by thread index
    if (e0 + 3 < E) {
        int4 r = __ldg((const int4*)(rowp + e0));
        int4 k;
        k.x = atomicAdd(&cnt[r.x], 1);
        k.y = atomicAdd(&cnt[r.y], 1);
        k.z = atomicAdd(&cnt[r.z], 1);
        k.w = atomicAdd(&cnt[r.w], 1);
        *(int4*)(rk + e0) = k;
    } else {
        for (int q = 0; q < 4; q++)
            if (e0 + q < E) rk[e0 + q] = atomicAdd(&cnt[__ldg(rowp + e0 + q)], 1);
    }
}

// -------------------- multi-block scan: partials over shard totals -------------------
__global__ void k_scanP(const int* __restrict__ cntAll, int* __restrict__ part, int N) {
    const int* cnt = cntAll + blockIdx.y * NSHARD * MAXN;
    __shared__ int sp[256];
    int tid = threadIdx.x;
    int s = blockIdx.x * SCHUNK + tid * 8;
    int sum = 0;
    #pragma unroll
    for (int i = 0; i < 8; i++) {
        int idx = s + i;
        if (idx < N)
            sum += cnt[idx] + cnt[MAXN + idx] + cnt[2 * MAXN + idx] + cnt[3 * MAXN + idx];
    }
    sp[tid] = sum;
    __syncthreads();
    for (int off = 128; off > 0; off >>= 1) {
        if (tid < off) sp[tid] += sp[tid + off];
        __syncthreads();
    }
    if (tid == 0) part[blockIdx.y * 512 + blockIdx.x] = sp[0];
}

// -------------------- scan partials (1 block) --------------------
__global__ void k_scanM(int* __restrict__ part, int* __restrict__ rpM,
                        int* __restrict__ rpA, int N, int G) {
    __shared__ int sp[1024];
    int tid = threadIdx.x;
    int g = tid >> 9, i = tid & 511;
    sp[tid] = (i < G) ? part[g * 512 + i] : 0;
    __syncthreads();
    for (int off = 1; off < 512; off <<= 1) {
        int v = (i >= off) ? sp[tid - off] : 0;
        __syncthreads();
        sp[tid] += v;
        __syncthreads();
    }
    int excl = (i == 0) ? 0 : sp[tid - 1];
    if (i < G) part[g * 512 + i] = excl;
    if (i == G - 1) { int* rp = g ? rpA : rpM; rp[N] = sp[tid]; }
}

// -------------------- final scan: rowptr + per-shard bases ---------------------------
__global__ void k_scanF(const int* __restrict__ cntAll, const int* __restrict__ part,
                        int* __restrict__ rpM, int* __restrict__ rpA,
                        int* __restrict__ sbAll, int N) {
    const int* cnt = cntAll + blockIdx.y * NSHARD * MAXN;
    int* sb = sbAll + blockIdx.y * NSHARD * MAXN;
    int* rp = blockIdx.y ? rpA : rpM;
    __shared__ int sp[256];
    int tid = threadIdx.x;
    int s = blockIdx.x * SCHUNK + tid * 8;
    int c0[8], c1[8], c2[8], c3[8];
    int tot[8];
    int sum = 0;
    #pragma unroll
    for (int i = 0; i < 8; i++) {
        int idx = s + i;
        if (idx < N) {
            c0[i] = cnt[idx];
            c1[i] = cnt[MAXN + idx];
            c2[i] = cnt[2 * MAXN + idx];
            c3[i] = cnt[3 * MAXN + idx];
        } else { c0[i] = c1[i] = c2[i] = c3[i] = 0; }
        tot[i] = c0[i] + c1[i] + c2[i] + c3[i];
        sum += tot[i];
    }
    sp[tid] = sum;
    __syncthreads();
    for (int off = 1; off < 256; off <<= 1) {
        int v = (tid >= off) ? sp[tid - off] : 0;
        __syncthreads();
        sp[tid] += v;
        __syncthreads();
    }
    int excl = part[blockIdx.y * 512 + blockIdx.x] + ((tid == 0) ? 0 : sp[tid - 1]);
    #pragma unroll
    for (int i = 0; i < 8; i++) {
        int idx = s + i;
        if (idx < N) {
            rp[idx] = excl;
            sb[idx]            = excl;
            sb[MAXN + idx]     = excl + c0[i];
            sb[2 * MAXN + idx] = excl + c0[i] + c1[i];
            sb[3 * MAXN + idx] = excl + c0[i] + c1[i] + c2[i];
            excl += tot[i];
        }
    }
}

// -------------------- scatter, atomic-free, sharded bases ----------------------------
__device__ __forceinline__ unsigned packe(float v, int col) {
    int q = __float2int_rn(v * 32767.f);
    q = max(0, min(q, 32767));
    return ((unsigned)q << 17) | (unsigned)col;
}

__global__ void k_scatter4(const int* __restrict__ mr, const int* __restrict__ mc,
                           const float* __restrict__ mv,
                           const int* __restrict__ ar, const int* __restrict__ ac,
                           const float* __restrict__ av,
                           const int* __restrict__ sbAll,
                           const int* __restrict__ rkM, const int* __restrict__ rkA,
                           unsigned* __restrict__ edM, unsigned* __restrict__ edA,
                           int Em, int Ea) {
    const int* rowp; const int* colp; const float* valp;
    const int* sbBase; const int* rk; unsigned* ed; int E;
    if (blockIdx.y == 0) { rowp = mr; colp = mc; valp = mv; sbBase = sbAll;                 rk = rkM; ed = edM; E = Em; }
    else                 { rowp = ar; colp = ac; valp = av; sbBase = sbAll + NSHARD * MAXN; rk = rkA; ed = edA; E = Ea; }
    int t = blockIdx.x * blockDim.x + threadIdx.x;
    int e0 = t * 4;
    const int* sb = sbBase + (t & (NSHARD - 1)) * MAXN;   // same shard rule as hist
    if (e0 + 3 < E) {
        int4   r = __ldg((const int4*)(rowp + e0));
        int4   c = __ldg((const int4*)(colp + e0));
        float4 v = __ldg((const float4*)(valp + e0));
        int4   k = __ldg((const int4*)(rk + e0));
        ed[__ldg(sb + r.x) + k.x] = packe(v.x, c.x);
        ed[__ldg(sb + r.y) + k.y] = packe(v.y, c.y);
        ed[__ldg(sb + r.z) + k.z] = packe(v.z, c.z);
        ed[__ldg(sb + r.w) + k.w] = packe(v.w, c.w);
    } else {
        for (int q = 0; q < 4; q++) {
            int e = e0 + q;
            if (e < E) {
                int pos = __ldg(sb + __ldg(rowp + e)) + __ldg(rk + e);
                ed[pos] = packe(__ldg(valp + e), __ldg(colp + e));
            }
        }
    }
}

// -------------------- CSR SpMM, BOTH graphs per launch (blockIdx.y) ------------------
__global__ void k_spmm2(const unsigned* __restrict__ edM, const int* __restrict__ rpM,
                        const __half* __restrict__ xM, __half* __restrict__ xnM,
                        const unsigned* __restrict__ edA, const int* __restrict__ rpA,
                        const __half* __restrict__ xA, __half* __restrict__ xnA,
                        int N_M, int N_A) {
    const unsigned* edges; const int* rowptr; const __half* x; __half* xnew; int N;
    if (blockIdx.y == 0) { edges = edM; rowptr = rpM; x = xM; xnew = xnM; N = N_M; }
    else                 { edges = edA; rowptr = rpA; x = xA; xnew = xnA; N = N_A; }

    int tid = blockIdx.x * blockDim.x + threadIdx.x;
    int r = tid >> 4;
    if (r >= N) return;
    int lane16 = threadIdx.x & 15;

    int s = __ldg(rowptr + r);
    int e = __ldg(rowptr + r + 1);

    const char* xb = (const char*)x + lane16 * 8;

    float ax = 0.f, ay = 0.f, az = 0.f, aw = 0.f;
    #pragma unroll 4
    for (int i = s; i < e; i++) {
        unsigned p = __ldg(edges + i);
        float v = (float)(p >> 17) * (1.f / 32767.f);
        uint2 hv = __ldg((const uint2*)(xb + ((p & 0x1FFFFu) << 7)));
        float2 f0 = __half22float2(*(__half2*)&hv.x);
        float2 f1 = __half22float2(*(__half2*)&hv.y);
        ax = fmaf(v, f0.x, ax);
        ay = fmaf(v, f0.y, ay);
        az = fmaf(v, f1.x, az);
        aw = fmaf(v, f1.y, aw);
    }

    __half2 h0 = __floats2half2_rn(ax, ay);
    __half2 h1 = __floats2half2_rn(az, aw);
    uint2 o;
    o.x = *(unsigned*)&h0;
    o.y = *(unsigned*)&h1;
    ((uint2*)(xnew + (size_t)r * D))[lane16] = o;
}

#define MMA_F16(c0,c1,c2,c3,a0,a1,a2,a3,b0,b1)                                      \
    asm volatile("mma.sync.aligned.m16n8k16.row.col.f32.f16.f16.f32 "               \
                 "{%0,%1,%2,%3},{%4,%5,%6,%7},{%8,%9},{%0,%1,%2,%3};"               \
                 : "+f"(c0), "+f"(c1), "+f"(c2), "+f"(c3)                           \
                 : "r"(a0), "r"(a1), "r"(a2), "r"(a3), "r"(b0), "r"(b1))

#define LDSM4(r0,r1,r2,r3,addr)                                                     \
    asm volatile("ldmatrix.sync.aligned.m8n8.x4.shared.b16 {%0,%1,%2,%3}, [%4];"    \
                 : "=r"(r0), "=r"(r1), "=r"(r2), "=r"(r3) : "r"(addr))

// -------------------- Text GEMM (fp16 HMMA m16n8k16) + fused epilogue -----------------
#define ASTRH 72
#define BSTRH 72
__global__ void k_textfinal(const float* __restrict__ tm, const float* __restrict__ ta,
                            const float* __restrict__ embM, const float* __restrict__ embA,
                            const __half* __restrict__ xh,
                            const __half* __restrict__ Wt, const float* __restrict__ bias,
                            float* __restrict__ out, int N_M, int N_A) {
    __shared__ __half As[64 * ASTRH];
    __shared__ __half BsT[64 * BSTRH];
    __shared__ float s_bias[64];
    __shared__ float s_nt[64];
    __shared__ float s_ng[64];

    const float* T;
    const float* emb;
    const __half* x1;
    float* dst;
    int N;
    if (blockIdx.y == 0) {
        T = tm; emb = embM; x1 = xh;                        dst = out;                   N = N_M;
    } else {
        T = ta; emb = embA; x1 = xh + 3 * (size_t)MAXN * D; dst = out + (size_t)N_M * D; N = N_A;
    }
    const __half* x2 = x1 + (size_t)MAXN * D;
    const __half* x3 = x2 + (size_t)MAXN * D;

    int r0 = blockIdx.x * 64;
    if (r0 >= N) return;

    int tid  = threadIdx.x;
    int wid  = tid >> 5;
    int lane = tid & 31;
    int gid  = lane >> 2;
    int tig  = lane & 3;
    int wr   = (wid >> 1) * 16;
    int wc   = (wid & 1) * 32;

    if (tid < 64) { s_bias[tid] = bias[tid]; s_nt[tid] = 0.f; s_ng[tid] = 0.f; }

    unsigned aBase = (unsigned)__cvta_generic_to_shared(
        As + (wr + (lane & 15)) * ASTRH + ((lane >> 4) << 3));
    unsigned bBase0 = (unsigned)__cvta_generic_to_shared(
        BsT + (wc + (lane & 7) + ((lane >> 4) << 3)) * BSTRH + (((lane >> 3) & 1) << 3));
    unsigned bBase1 = bBase0 + 16 * BSTRH * 2;

    float c[4][4];
    #pragma unroll
    for (int j = 0; j < 4; j++)
        #pragma unroll
        for (int q = 0; q < 4; q++) c[j][q] = 0.f;

    for (int k0 = 0; k0 < DTXT; k0 += 64) {
        #pragma unroll
        for (int it = 0; it < 4; it++) {
            int fi = tid + it * 256;
            int rr = fi >> 4;
            int kq = fi & 15;
            int gr = r0 + rr;
            float4 v = (gr < N) ? __ldg(((const float4*)(T + (size_t)gr * DTXT + k0)) + kq)
                                : make_float4(0.f, 0.f, 0.f, 0.f);
            __half2 h0 = __floats2half2_rn(v.x, v.y);
            __half2 h1 = __floats2half2_rn(v.z, v.w);
            uint2 o;
            o.x = *(unsigned*)&h0;
            o.y = *(unsigned*)&h1;
            *(uint2*)(As + rr * ASTRH + kq * 4) = o;
        }
        #pragma unroll
        for (int it = 0; it < 2; it++) {
            int fi = tid + it * 256;
            int nn = fi >> 3;
            int kq = fi & 7;
            uint4 v = *(const uint4*)(Wt + (size_t)nn * DTXT + k0 + kq * 8);
            *(uint4*)(BsT + nn * BSTRH + kq * 8) = v;
        }
        __syncthreads();

        #pragma unroll
        for (int kk = 0; kk < 64; kk += 16) {
            unsigned a0, a1, a2, a3, b0, b1, b2, b3, b4, b5, b6, b7;
            LDSM4(a0, a1, a2, a3, aBase  + kk * 2);
            LDSM4(b0, b1, b2, b3, bBase0 + kk * 2);
            LDSM4(b4, b5, b6, b7, bBase1 + kk * 2);
            MMA_F16(c[0][0], c[0][1], c[0][2], c[0][3], a0, a1, a2, a3, b0, b1);
            MMA_F16(c[1][0], c[1][1], c[1][2], c[1][3], a0, a1, a2, a3, b2, b3);
            MMA_F16(c[2][0], c[2][1], c[2][2], c[2][3], a0, a1, a2, a3, b4, b5);
            MMA_F16(c[3][0], c[3][1], c[3][2], c[3][3], a0, a1, a2, a3, b6, b7);
        }
        __syncthreads();
    }

    int lrA = wr + gid, lrB = lrA + 8;
    int grA = r0 + lrA, grB = r0 + lrB;
    bool okA = grA < N, okB = grB < N;

    float tv[4][4];
    float2 gA[4], gB[4];
    float stA = 0.f, stB = 0.f, sgA = 0.f, sgB = 0.f;
    #pragma unroll
    for (int j = 0; j < 4; j++) {
        int col = wc + j * 8 + 2 * tig;
        float b0 = s_bias[col], b1 = s_bias[col + 1];
        float t0 = c[j][0] + b0, t1 = c[j][1] + b1;
        float t2 = c[j][2] + b0, t3 = c[j][3] + b1;
        tv[j][0] = t0; tv[j][1] = t1; tv[j][2] = t2; tv[j][3] = t3;
        stA += t0 * t0 + t1 * t1;
        stB += t2 * t2 + t3 * t3;

        float2 ga = make_float2(0.f, 0.f), gb = make_float2(0.f, 0.f);
        if (okA) {
            size_t off = (size_t)grA * D + col;
            float2 e = *(const float2*)(emb + off);
            float2 f1 = __half22float2(*(const __half2*)(x1 + off));
            float2 f2 = __half22float2(*(const __half2*)(x2 + off));
            float2 f3 = __half22float2(*(const __half2*)(x3 + off));
            ga = make_float2(e.x + f1.x + f2.x + f3.x, e.y + f1.y + f2.y + f3.y);
        }
        if (okB) {
            size_t off = (size_t)grB * D + col;
            float2 e = *(const float2*)(emb + off);
            float2 f1 = __half22float2(*(const __half2*)(x1 + off));
            float2 f2 = __half22float2(*(const __half2*)(x2 + off));
            float2 f3 = __half22float2(*(const __half2*)(x3 + off));
            gb = make_float2(e.x + f1.x + f2.x + f3.x, e.y + f1.y + f2.y + f3.y);
        }
        gA[j] = ga; gB[j] = gb;
        sgA += ga.x * ga.x + ga.y * ga.y;
        sgB += gb.x * gb.x + gb.y * gb.y;
    }
    #pragma unroll
    for (int m = 1; m < 4; m <<= 1) {
        stA += __shfl_xor_sync(0xffffffffu, stA, m);
        stB += __shfl_xor_sync(0xffffffffu, stB, m);
        sgA += __shfl_xor_sync(0xffffffffu, sgA, m);
        sgB += __shfl_xor_sync(0xffffffffu, sgB, m);
    }
    if (tig == 0) {
        atomicAdd(&s_nt[lrA], stA);
        atomicAdd(&s_nt[lrB], stB);
        atomicAdd(&s_ng[lrA], sgA);
        atomicAdd(&s_ng[lrB], sgB);
    }
    __syncthreads();

    float intA = 1.f / fmaxf(sqrtf(s_nt[lrA]), 1e-12f);
    float intB = 1.f / fmaxf(sqrtf(s_nt[lrB]), 1e-12f);
    float ingA = 1.f / fmaxf(sqrtf(s_ng[lrA]), 1e-12f);
    float ingB = 1.f / fmaxf(sqrtf(s_ng[lrB]), 1e-12f);

    #pragma unroll
    for (int j = 0; j < 4; j++) {
        int col = wc + j * 8 + 2 * tig;
        if (okA)
            *(float2*)(dst + (size_t)grA * D + col) =
                make_float2(0.5f * (gA[j].x * ingA + tv[j][0] * intA),
                            0.5f * (gA[j].y * ingA + tv[j][1] * intA));
        if (okB)
            *(float2*)(dst + (size_t)grB * D + col) =
                make_float2(0.5f * (gB[j].x * ingB + tv[j][2] * intB),
                            0.5f * (gB[j].y * ingB + tv[j][3] * intB));
    }
}

// -------------------- launch --------------------
extern "C" void kernel_launch(void* const* d_in, const int* in_sizes, int n_in,
                              void* d_out, int out_size) {
    const int*   m_row = (const int*)d_in[0];
    const int*   m_col = (const int*)d_in[1];
    const float* m_val = (const float*)d_in[2];
    const int*   a_row = (const int*)d_in[3];
    const int*   a_col = (const int*)d_in[4];
    const float* a_val = (const float*)d_in[5];
    const float* m_txt = (const float*)d_in[6];
    const float* a_txt = (const float*)d_in[7];
    const float* m_emb = (const float*)d_in[8];
    const float* a_emb = (const float*)d_in[9];
    const float* W     = (const float*)d_in[10];
    const float* bias  = (const float*)d_in[11];

    int E_M = in_sizes[0];
    int E_A = in_sizes[3];
    int N_M = in_sizes[8] / D;
    int N_A = in_sizes[9] / D;

    float* out = (float*)d_out;

    unsigned* edM;  cudaGetSymbolAddress((void**)&edM,  g_edgesM);
    unsigned* edA;  cudaGetSymbolAddress((void**)&edA,  g_edgesA);
    int*    rkM;   cudaGetSymbolAddress((void**)&rkM,   g_rankM);
    int*    rkA;   cudaGetSymbolAddress((void**)&rkA,   g_rankA);
    __half* embHM; cudaGetSymbolAddress((void**)&embHM, g_embHM);
    __half* embHA; cudaGetSymbolAddress((void**)&embHA, g_embHA);
    __half* xh;    cudaGetSymbolAddress((void**)&xh,    g_xh);
    int*    rpM;   cudaGetSymbolAddress((void**)&rpM,   g_rowptrM);
    int*    rpA;   cudaGetSymbolAddress((void**)&rpA,   g_rowptrA);
    int*    cnt;   cudaGetSymbolAddress((void**)&cnt,   g_cnt);
    int*    sb;    cudaGetSymbolAddress((void**)&sb,    g_sb);
    int*    part;  cudaGetSymbolAddress((void**)&part,  g_part);
    __half* wt;    cudaGetSymbolAddress((void**)&wt,    g_wt);

    __half* x1M = xh;
    __half* x2M = x1M + (size_t)MAXN * D;
    __half* x3M = x2M + (size_t)MAXN * D;
    __half* x1A = x3M + (size_t)MAXN * D;
    __half* x2A = x1A + (size_t)MAXN * D;
    __half* x3A = x2A + (size_t)MAXN * D;

    const int TB = 256;
    int maxE = (E_M > E_A) ? E_M : E_A;
    int maxN = (N_M > N_A) ? N_M : N_A;
    int eg4  = (maxE + 4 * TB - 1) / (4 * TB);
    int sgX  = (maxN * 16 + TB - 1) / TB;
    int G    = (N_M + SCHUNK - 1) / SCHUNK;     // N_M == N_A
    int h4   = (maxN * D / 4 + TB - 1) / TB;

    // prep
    k_prepw<<<(D * DTXT + TB - 1) / TB, TB>>>(W, wt, D * DTXT);
    cudaMemsetAsync(cnt, 0, 2 * NSHARD * (size_t)MAXN * sizeof(int));

    // CSR builds (sharded counters)
    dim3 eg(eg4, 2), sg(G, 2), pg(h4, 2), mg(sgX, 2);
    k_hist4<<<eg, TB>>>(m_row, a_row, cnt, rkM, rkA, E_M, E_A);
    k_scanP<<<sg, TB>>>(cnt, part, N_M);
    k_scanM<<<1, 1024>>>(part, rpM, rpA, N_M, G);
    k_scanF<<<sg, TB>>>(cnt, part, rpM, rpA, sb, N_M);
    k_scatter4<<<eg, TB>>>(m_row, m_col, m_val, a_row, a_col, a_val,
                           sb, rkM, rkA, edM, edA, E_M, E_A);

    // emb -> fp16 (both graphs)
    k_prephalf2<<<pg, TB>>>((const float4*)m_emb, (const float4*)a_emb,
                            (uint2*)embHM, (uint2*)embHA, N_M * D / 4, N_A * D / 4);

    // 3 propagation layers, both graphs per launch
    k_spmm2<<<mg, TB>>>(edM, rpM, embHM, x1M, edA, rpA, embHA, x1A, N_M, N_A);
    k_spmm2<<<mg, TB>>>(edM, rpM, x1M,   x2M, edA, rpA, x1A,   x2A, N_M, N_A);
    k_spmm2<<<mg, TB>>>(edM, rpM, x2M,   x3M, edA, rpA, x2A,   x3A, N_M, N_A);

    // text GEMM + acc assembly + norms + combine
    dim3 grid((maxN + 63) / 64, 2);
    k_textfinal<<<grid, 256>>>(m_txt, a_txt, m_emb, a_emb, xh, wt, bias, out, N_M, N_A);
}